// round 17
// baseline (speedup 1.0000x reference)
#include <cuda_runtime.h>
#include <cstdint>

#define BB   32
#define TT   1024
#define HID  512
#define G4   2048            // 4*HID
#define MROWS (BB*TT)        // 32768
#define NCTA 128
#define OUT_MAIN (BB*TT*HID) // 16777216

typedef unsigned long long ull;

__device__ __forceinline__ ull pack2(float x) {
    ull d; asm("mov.b64 %0, {%1, %1};" : "=l"(d) : "f"(x)); return d;
}
__device__ __forceinline__ ull fma2(ull a, ull b, ull c) {
    ull d; asm("fma.rn.f32x2 %0, %1, %2, %3;" : "=l"(d) : "l"(a), "l"(b), "l"(c)); return d;
}
__device__ __forceinline__ void unpack2(ull v, float& lo, float& hi) {
    asm("mov.b64 {%0, %1}, %2;" : "=f"(lo), "=f"(hi) : "l"(v));
}
__device__ __forceinline__ ull tagpack(float h, unsigned tag) {
    ull d; asm("mov.b64 %0, {%1, %2};" : "=l"(d) : "f"(h), "r"(tag)); return d;
}

// -------------------- device scratch --------------------
__device__ float g_G[(size_t)MROWS * G4];           // precomputed input-side gates
__device__ float g_Y0[(size_t)(TT + 1) * BB * HID]; // layer-0 h outputs (slot t+1 = h_t)
__device__ ull g_ht[(size_t)TT * BB * HID];         // tagged h words: slot t = h_{t-1}
__device__ unsigned g_epoch;                        // bumped +TT by each gemm launch

// -------------------- big GEMM (FFMA2); block(0,0) bumps the tag epoch ----------
template <int MODE>
__global__ __launch_bounds__(256) void gemm_kernel(
    const float* __restrict__ A,
    const float* __restrict__ W,
    const float* __restrict__ bih,
    const float* __restrict__ bhh,
    float* __restrict__ Gout)
{
    __shared__ float As[16 * 132];
    __shared__ float Bs[16 * 66];

    const int tid = threadIdx.x;
    const int bm = blockIdx.y;
    const int bn = blockIdx.x;
    const int ty = tid >> 4;
    const int tx = tid & 15;

    if (bm == 0 && bn == 0 && tid == 0)
        g_epoch += TT;                       // unique tag range per recur launch

    ull acc2[8][2];
#pragma unroll
    for (int i = 0; i < 8; i++) { acc2[i][0] = 0ULL; acc2[i][1] = 0ULL; }

    for (int kt = 0; kt < HID; kt += 16) {
#pragma unroll
        for (int q = 0; q < 2; q++) {
            int idx = tid + q * 256;
            int lrow = idx >> 2;
            int lk = (idx & 3) << 2;
            int r = bm * 128 + lrow;
            const float* ap;
            if (MODE == 0)
                ap = A + ((size_t)(r & 31) * TT + (size_t)(r >> 5)) * HID;
            else
                ap = A + (size_t)r * HID;
            float4 v = *(const float4*)(ap + kt + lk);
            As[(lk + 0) * 132 + lrow] = v.x;
            As[(lk + 1) * 132 + lrow] = v.y;
            As[(lk + 2) * 132 + lrow] = v.z;
            As[(lk + 3) * 132 + lrow] = v.w;
        }
        {
            int ln = tid >> 2;
            int lk = (tid & 3) << 2;
            float4 v = *(const float4*)(W + (size_t)(bn * 64 + ln) * HID + kt + lk);
            Bs[(lk + 0) * 66 + ln] = v.x;
            Bs[(lk + 1) * 66 + ln] = v.y;
            Bs[(lk + 2) * 66 + ln] = v.z;
            Bs[(lk + 3) * 66 + ln] = v.w;
        }
        __syncthreads();

#pragma unroll
        for (int k = 0; k < 16; k++) {
            float4 a0 = *(const float4*)&As[k * 132 + 4 * ty];
            float4 a1 = *(const float4*)&As[k * 132 + 64 + 4 * ty];
            ull bp0 = *(const ull*)&Bs[k * 66 + 2 * tx];
            ull bp1 = *(const ull*)&Bs[k * 66 + 32 + 2 * tx];
            float av[8] = {a0.x, a0.y, a0.z, a0.w, a1.x, a1.y, a1.z, a1.w};
#pragma unroll
            for (int i = 0; i < 8; i++) {
                ull ad = pack2(av[i]);
                acc2[i][0] = fma2(ad, bp0, acc2[i][0]);
                acc2[i][1] = fma2(ad, bp1, acc2[i][1]);
            }
        }
        __syncthreads();
    }

    int c0 = bn * 64 + 2 * tx;
    int c1 = c0 + 32;
    float bias00 = bih[c0] + bhh[c0];
    float bias01 = bih[c0 + 1] + bhh[c0 + 1];
    float bias10 = bih[c1] + bhh[c1];
    float bias11 = bih[c1 + 1] + bhh[c1 + 1];
#pragma unroll
    for (int i = 0; i < 8; i++) {
        int m = (i < 4) ? (4 * ty + i) : (64 + 4 * ty + i - 4);
        size_t r = (size_t)(bm * 128 + m);
        float x, y;
        unpack2(acc2[i][0], x, y);
        *(float2*)(Gout + r * G4 + c0) = make_float2(x + bias00, y + bias01);
        unpack2(acc2[i][1], x, y);
        *(float2*)(Gout + r * G4 + c1) = make_float2(x + bias10, y + bias11);
    }
}

// -------------------- persistent recurrence: tagged-payload sync -----------------
// Group g = CTAs 32g..32g+31, batches 8g..8g+7. CTA cl: units j0=16cl (64 rows).
// Warp w (of 16): k-slice [32w,32w+32). Consumer poll: lane polls the 8 tagged
// words (batch q, unit kbase+lane) of slot t; tag==ebase+t -> payload IS h.
// Producer: act thread (u,b) stores (tag=ebase+t+1, h) to slot t+1. No fences,
// no flags.  One __syncthreads per step (scatter->reduce).
//
// Smem (bytes):
//   ws  : float[64][516]  @ 0       (132096)
//   h_s : float[8][516]   @ 132096  (16512)
//   red : float[512*17]   @ 148608  (34816)
#define SM_WS    0
#define SM_HS    132096
#define SM_RED   148608
#define SM_TOTAL 183424

__global__ __launch_bounds__(512, 1) void recur_kernel(
    int layer,
    const float* __restrict__ Whh,
    const float* __restrict__ h0l,
    const float* __restrict__ c0l,
    float* __restrict__ out)
{
    extern __shared__ char smraw[];
    float* ws  = (float*)(smraw + SM_WS);
    float* h_s = (float*)(smraw + SM_HS);
    float* red = (float*)(smraw + SM_RED);

    const int tid = threadIdx.x;
    const int cta = blockIdx.x;
    const int grp = cta >> 5;
    const int cl  = cta & 31;
    const int j0  = cl * 16;
    const int bbase = grp * 8;

    const unsigned ebase = g_epoch;          // same value for all CTAs this launch

    // ---- load Whh slice: 64 rows, eighth-row per thread ----
    {
        int r = tid >> 3, part = tid & 7;
        const float* src = Whh + ((size_t)((r >> 4) * HID + j0 + (r & 15))) * HID + part * 64;
        float* dst = ws + r * 516 + part * 64;
#pragma unroll
        for (int i = 0; i < 16; i++)
            *(float4*)(dst + i * 4) = *(const float4*)(src + i * 4);
    }

    // ---- act threads (tid<128): u=tid&15, bg=(tid>>4)&1, j=tid>>5, b=4bg+j ----
    const bool act = (tid < 128);
    const int au = tid & 15;
    const int abg = (tid >> 4) & 1;
    const int aj = tid >> 5;
    const int ab = 4 * abg + aj;
    const int cbase = au + 16 * abg + 128 * aj;   // + 32*i for gate type i
    float creg = 0.f;
    if (act) creg = c0l[(size_t)(bbase + ab) * HID + j0 + au];
    __syncthreads();

    const int widx = tid >> 5;
    const int lane = tid & 31;
    const int rg = lane & 15;
    const int bgc = lane >> 4;
    const int kbase = widx * 32;

    const float* wp = ws + rg * 516 + kbase;       // rows rg+16i at +i*8256
    const float* hp = h_s + 4 * bgc * 516 + kbase; // batches 4bgc+j at +j*516

    float* outh = out + OUT_MAIN;
    float* outc = out + OUT_MAIN + 2 * BB * HID;

    for (int t = 0; t < TT; t++) {
        // ---- act threads prefetch their 4 input-side gate values ----
        float Gv[4];
        if (act) {
            const float* gro = g_G + ((size_t)t * BB + bbase + ab) * G4 + j0 + au;
#pragma unroll
            for (int q = 0; q < 4; q++) Gv[q] = gro[q * HID];
        }

        // ---- acquire h_{t-1} into h_s (warp's k-slice x 8 batches) ----
        if (t == 0) {
            // initial state: plain loads from h0l
#pragma unroll
            for (int q = 0; q < 2; q++) {
                int idx = lane + 32 * q;
                int row = idx >> 3;
                int off = (idx & 7) << 2;
                float4 v = *(const float4*)(h0l + (size_t)(bbase + row) * HID + kbase + off);
                *(float4*)(h_s + row * 516 + kbase + off) = v;
            }
        } else {
            // tagged poll: lane covers (batch q, unit kbase+lane), q = 0..7
            const ull* hb = g_ht + (size_t)t * BB * HID + (size_t)bbase * HID + kbase + lane;
            unsigned tag = ebase + (unsigned)t;
            unsigned pend = 0xffu;
            int sp = 0;
            while (pend) {
#pragma unroll
                for (int q = 0; q < 8; q++) {
                    if (pend & (1u << q)) {
                        ull v;
                        asm volatile("ld.relaxed.gpu.global.b64 %0, [%1];"
                                     : "=l"(v) : "l"(hb + (size_t)q * HID) : "memory");
                        if ((unsigned)(v >> 32) == tag) {
                            float hval; unsigned hi_;
                            asm("mov.b64 {%0, %1}, %2;" : "=f"(hval), "=r"(hi_) : "l"(v));
                            h_s[q * 516 + kbase + lane] = hval;
                            pend &= ~(1u << q);
                        }
                    }
                }
                if (pend && ++sp > 128) __nanosleep(20);
            }
        }
        __syncwarp();

        // ---- mainloop: 4x4 tile over 32 k (8 iters) ----
        ull acc[4][4];
#pragma unroll
        for (int i = 0; i < 4; i++)
#pragma unroll
            for (int j = 0; j < 4; j++) acc[i][j] = 0ULL;

#pragma unroll
        for (int kk = 0; kk < 32; kk += 4) {
            ulonglong2 hv0 = *(const ulonglong2*)(hp + 0 * 516 + kk);
            ulonglong2 hv1 = *(const ulonglong2*)(hp + 1 * 516 + kk);
            ulonglong2 hv2 = *(const ulonglong2*)(hp + 2 * 516 + kk);
            ulonglong2 hv3 = *(const ulonglong2*)(hp + 3 * 516 + kk);
#pragma unroll
            for (int i = 0; i < 4; i++) {
                ulonglong2 wv = *(const ulonglong2*)(wp + i * 8256 + kk);
                acc[i][0] = fma2(hv0.x, wv.x, acc[i][0]);
                acc[i][0] = fma2(hv0.y, wv.y, acc[i][0]);
                acc[i][1] = fma2(hv1.x, wv.x, acc[i][1]);
                acc[i][1] = fma2(hv1.y, wv.y, acc[i][1]);
                acc[i][2] = fma2(hv2.x, wv.x, acc[i][2]);
                acc[i][2] = fma2(hv2.y, wv.y, acc[i][2]);
                acc[i][3] = fma2(hv3.x, wv.x, acc[i][3]);
                acc[i][3] = fma2(hv3.y, wv.y, acc[i][3]);
            }
        }

        // ---- scatter k-split partials: red[(lane+32(i+4j))*17 + widx] ----
#pragma unroll
        for (int i = 0; i < 4; i++)
#pragma unroll
            for (int j = 0; j < 4; j++) {
                float lo, hi;
                unpack2(acc[i][j], lo, hi);
                red[(lane + 32 * (i + 4 * j)) * 17 + widx] = lo + hi;
            }
        __syncthreads();   // the only block-wide sync per step

        // ---- act threads: fused reduce + activation + tagged publish ----
        if (act) {
            float x[4];
#pragma unroll
            for (int i = 0; i < 4; i++) {
                const float* rp = red + (cbase + 32 * i) * 17;
                float s0 = rp[0] + rp[1], s1 = rp[2] + rp[3];
                float s2 = rp[4] + rp[5], s3 = rp[6] + rp[7];
                float s4 = rp[8] + rp[9], s5 = rp[10] + rp[11];
                float s6 = rp[12] + rp[13], s7 = rp[14] + rp[15];
                x[i] = Gv[i] + (((s0 + s1) + (s2 + s3)) + ((s4 + s5) + (s6 + s7)));
            }
            float iv = 1.f / (1.f + __expf(-x[0]));
            float fv = 1.f / (1.f + __expf(-x[1]));
            float gv = 1.f - 2.f / (__expf(2.f * x[2]) + 1.f);
            float ov = 1.f / (1.f + __expf(-x[3]));
            float c = fv * creg + iv * gv;
            creg = c;
            float h = ov * (1.f - 2.f / (__expf(2.f * c) + 1.f));

            // tagged publish for step-t+1 consumers (skip last step: no consumers)
            if (t < TT - 1) {
                ull w = tagpack(h, ebase + (unsigned)(t + 1));
                ull* dst = g_ht + (size_t)(t + 1) * BB * HID
                         + (size_t)(bbase + ab) * HID + j0 + au;
                asm volatile("st.relaxed.gpu.global.b64 [%0], %1;"
                             :: "l"(dst), "l"(w) : "memory");
            }
            // plain copies (consumed only across launch boundaries / by harness)
            if (layer == 0) {
                g_Y0[((size_t)(t + 1) * BB + bbase + ab) * HID + j0 + au] = h;
            } else {
                out[((size_t)(bbase + ab) * TT + t) * HID + j0 + au] = h;
            }
            if (t == TT - 1) {
                outh[(size_t)(layer * BB + bbase + ab) * HID + j0 + au] = h;
                outc[(size_t)(layer * BB + bbase + ab) * HID + j0 + au] = creg;
            }
        }
        // no tail barrier: consumers sync via tags; red reuse has ~3000cyc margin
    }
}

// -------------------- launch --------------------
extern "C" void kernel_launch(void* const* d_in, const int* in_sizes, int n_in,
                              void* d_out, int out_size) {
    const float* input = (const float*)d_in[0];
    const float* h0    = (const float*)d_in[1];
    const float* c0    = (const float*)d_in[2];
    const float* W_ih  = (const float*)d_in[3];
    const float* W_hh  = (const float*)d_in[4];
    const float* b_ih  = (const float*)d_in[5];
    const float* b_hh  = (const float*)d_in[6];
    float* out = (float*)d_out;

    cudaFuncSetAttribute(recur_kernel, cudaFuncAttributeMaxDynamicSharedMemorySize, SM_TOTAL);

    float* Gptr;
    cudaGetSymbolAddress((void**)&Gptr, g_G);
    float* Y0ptr;
    cudaGetSymbolAddress((void**)&Y0ptr, g_Y0);

    dim3 ggrid(32, 256);

    // Layer 0 (gemm<0> bumps epoch, stream-ordered before recur)
    gemm_kernel<0><<<ggrid, 256>>>(input, W_ih, b_ih, b_hh, Gptr);
    recur_kernel<<<NCTA, 512, SM_TOTAL>>>(0, W_hh, h0, c0, out);

    // Layer 1 (gemm<1> bumps epoch again; input = layer-0 outputs)
    gemm_kernel<1><<<ggrid, 256>>>(Y0ptr + BB * HID, W_ih + (size_t)G4 * HID,
                                   b_ih + G4, b_hh + G4, Gptr);
    recur_kernel<<<NCTA, 512, SM_TOTAL>>>(1, W_hh + (size_t)G4 * HID,
                                          h0 + BB * HID, c0 + BB * HID, out);
}